// round 8
// baseline (speedup 1.0000x reference)
#include <cuda_runtime.h>
#include <cuda_bf16.h>
#include <math_constants.h>
#include <cstdint>

#define L     8192
#define D     64
#define BM    128            // query rows per CTA
#define NCH   8
#define CHUNK 1024           // L / NCH
#define BN    64             // key-tile width
#define NTIL  16             // CHUNK / BN
#define NT    256

// ---------------- scratch (__device__ globals; no allocation allowed) -------
__device__ float g_mp[NCH * L];
__device__ float g_lp[NCH * L];
// 2-limb bf16 versions of Q, K, V (prep kernel fills once)
__device__ __nv_bfloat16 gQh[L * D], gQl[L * D];
__device__ __nv_bfloat16 gKh[L * D], gKl[L * D];
__device__ __nv_bfloat16 gVh[L * D], gVl[L * D];

// ---------------- helpers ---------------------------------------------------
__device__ __forceinline__ uint32_t smem_to_u32(const void* p) {
    uint32_t a;
    asm("{ .reg .u64 t; cvta.to.shared.u64 t, %1; cvt.u32.u64 %0, t; }"
        : "=r"(a) : "l"(p));
    return a;
}
#define CP_ASYNC16(dst, src) \
    asm volatile("cp.async.cg.shared.global [%0], [%1], 16;" \
                 :: "r"(dst), "l"(src) : "memory")
#define CP_COMMIT() asm volatile("cp.async.commit_group;" ::: "memory")
#define CP_WAIT(n)  asm volatile("cp.async.wait_group %0;" :: "n"(n) : "memory")

__device__ __forceinline__ void ldsm_x4(uint32_t* r, uint32_t a) {
    asm volatile("ldmatrix.sync.aligned.m8n8.x4.shared.b16 {%0,%1,%2,%3}, [%4];"
                 : "=r"(r[0]), "=r"(r[1]), "=r"(r[2]), "=r"(r[3]) : "r"(a));
}
__device__ __forceinline__ void ldsm_x4_t(uint32_t* r, uint32_t a) {
    asm volatile("ldmatrix.sync.aligned.m8n8.x4.trans.shared.b16 {%0,%1,%2,%3}, [%4];"
                 : "=r"(r[0]), "=r"(r[1]), "=r"(r[2]), "=r"(r[3]) : "r"(a));
}
__device__ __forceinline__ void mma_bf16(float* c, const uint32_t* a,
                                         uint32_t b0, uint32_t b1) {
    asm volatile("mma.sync.aligned.m16n8k16.row.col.f32.bf16.bf16.f32 "
                 "{%0,%1,%2,%3}, {%4,%5,%6,%7}, {%8,%9}, {%0,%1,%2,%3};"
                 : "+f"(c[0]), "+f"(c[1]), "+f"(c[2]), "+f"(c[3])
                 : "r"(a[0]), "r"(a[1]), "r"(a[2]), "r"(a[3]), "r"(b0), "r"(b1));
}
__device__ __forceinline__ void split2(float x, float y,
                                       __nv_bfloat162& h2, __nv_bfloat162& l2) {
    __nv_bfloat16 hx = __float2bfloat16(x);
    __nv_bfloat16 hy = __float2bfloat16(y);
    h2.x = hx; h2.y = hy;
    l2.x = __float2bfloat16(x - __bfloat162float(hx));
    l2.y = __float2bfloat16(y - __bfloat162float(hy));
}
// SW128 swizzle: 128B rows, 16B chunks; chunk c of row r lives at c^(r&7)
__device__ __forceinline__ uint32_t swo(int r, int c16) {
    return (uint32_t)(r * 128 + ((c16 ^ (r & 7)) << 4));
}

// kernel A smem offsets
#define AQH 0
#define AQL 16384
#define AK0 32768              // K buf b at AK0 + b*16384 (hi +0, lo +8192)
#define A_STATS 65536
#define A_SMEM  (65536 + 3072)
// kernel B smem offsets
#define BQH 0
#define BQL 16384
#define BPH 32768
#define BPL 49152
#define BKH 65536
#define BKL 73728
#define BVH 81920
#define BVL 90112
#define B_STATS 98304
#define B_SMEM  (98304 + 1024)

// ---------------------------------------------------------------------------
// Prep: split Q, K, V into bf16 hi/lo limb arrays
// ---------------------------------------------------------------------------
__global__ void prep_kernel(const float* __restrict__ Q,
                            const float* __restrict__ Km,
                            const float* __restrict__ V) {
    const int idx = blockIdx.x * 256 + threadIdx.x;    // float2 index
    const float* src; __nv_bfloat16 *dh, *dl;
    if (blockIdx.y == 0)      { src = Q;  dh = gQh; dl = gQl; }
    else if (blockIdx.y == 1) { src = Km; dh = gKh; dl = gKl; }
    else                      { src = V;  dh = gVh; dl = gVl; }
    const float2 v = *(const float2*)&src[idx * 2];
    __nv_bfloat162 h2, l2; split2(v.x, v.y, h2, l2);
    *(__nv_bfloat162*)&dh[idx * 2] = h2;
    *(__nv_bfloat162*)&dl[idx * 2] = l2;
}

__global__ void zero_o_kernel(float* __restrict__ O) {
    const int idx = blockIdx.x * 256 + threadIdx.x;
    *(float4*)&O[idx * 4] = make_float4(0.f, 0.f, 0.f, 0.f);
}

// ---------------------------------------------------------------------------
// Kernel A: per-chunk (m,l) stats from Q K^T (no S stores)
// warps: 4 row x 2 col groups; warp tile 32x32; K double-buffered cp.async
// ---------------------------------------------------------------------------
__global__ __launch_bounds__(NT, 3) void statsA_kernel() {
    extern __shared__ char smem[];
    const uint32_t sb = smem_to_u32(smem);
    const int tid  = threadIdx.x;
    const int lane = tid & 31;
    const int w    = tid >> 5;
    const int wr   = (w & 3) * 32;
    const int wc   = (w >> 2) * 32;
    const int cg   = w >> 2;
    const int rowblk  = blockIdx.y * BM;
    const int colbase = blockIdx.x * CHUNK;

    float* row_m = (float*)(smem + A_STATS);        // [128]
    float* row_l = row_m + 128;                     // [128]
    float* pm    = row_l + 128;                     // [2][128]
    float* pl    = pm + 256;                        // [2][128]

#pragma unroll
    for (int i = 0; i < 8; i++) {
        const int idx = tid + i * NT;                // 2048 chunks
        const int limb = idx >> 10, rem = idx & 1023;
        const int r = rem >> 3, c = rem & 7;
        const __nv_bfloat16* src =
            (limb ? gQl : gQh) + (size_t)(rowblk + r) * D + c * 8;
        CP_ASYNC16(sb + (limb ? AQL : AQH) + swo(r, c), src);
    }
#pragma unroll
    for (int i = 0; i < 4; i++) {
        const int idx = tid + i * NT;                // 1024 chunks
        const int limb = idx >> 9, rem = idx & 511;
        const int r = rem >> 3, c = rem & 7;
        const __nv_bfloat16* src =
            (limb ? gKl : gKh) + (size_t)(colbase + r) * D + c * 8;
        CP_ASYNC16(sb + AK0 + limb * 8192 + swo(r, c), src);
    }
    CP_COMMIT();
    if (tid < 128) { row_m[tid] = -CUDART_INF_F; row_l[tid] = 0.0f; }

    const int a_row = (lane & 7) + (lane & 8);
    const int a_c   = (lane >> 4) & 1;
    const int b_n   = (lane & 7) + ((lane >> 4) & 1) * 8;
    const int b_c   = (lane >> 3) & 1;

    for (int t = 0; t < NTIL; t++) {
        if (t + 1 < NTIL) {
            const int kb = colbase + (t + 1) * BN;
            const uint32_t kd = sb + AK0 + ((t + 1) & 1) * 16384;
#pragma unroll
            for (int i = 0; i < 4; i++) {
                const int idx = tid + i * NT;
                const int limb = idx >> 9, rem = idx & 511;
                const int r = rem >> 3, c = rem & 7;
                const __nv_bfloat16* src =
                    (limb ? gKl : gKh) + (size_t)(kb + r) * D + c * 8;
                CP_ASYNC16(kd + limb * 8192 + swo(r, c), src);
            }
            CP_COMMIT();
            CP_WAIT(1);
        } else {
            CP_WAIT(0);
        }
        __syncthreads();

        const uint32_t skh = sb + AK0 + (t & 1) * 16384;
        const uint32_t skl = skh + 8192;

        float acc[2][4][4];
#pragma unroll
        for (int i = 0; i < 2; i++)
#pragma unroll
            for (int j = 0; j < 4; j++)
#pragma unroll
                for (int e = 0; e < 4; e++) acc[i][j][e] = 0.0f;

#pragma unroll
        for (int ks = 0; ks < 4; ks++) {
            uint32_t aH[2][4], aL[2][4];
#pragma unroll
            for (int i = 0; i < 2; i++) {
                const uint32_t ao = swo(wr + 16 * i + a_row, ks * 2 + a_c);
                ldsm_x4(aH[i], sb + AQH + ao);
                ldsm_x4(aL[i], sb + AQL + ao);
            }
#pragma unroll
            for (int jj = 0; jj < 2; jj++) {
                const uint32_t bo = swo(wc + jj * 16 + b_n, ks * 2 + b_c);
                uint32_t bh[4], bl[4];
                ldsm_x4(bh, skh + bo);
                ldsm_x4(bl, skl + bo);
#pragma unroll
                for (int i = 0; i < 2; i++)
#pragma unroll
                    for (int p = 0; p < 2; p++) {
                        float* c = acc[i][2 * jj + p];
                        mma_bf16(c, aH[i], bh[2 * p], bh[2 * p + 1]);
                        mma_bf16(c, aH[i], bl[2 * p], bl[2 * p + 1]);
                        mma_bf16(c, aL[i], bh[2 * p], bh[2 * p + 1]);
                    }
            }
        }

        // stats-only epilogue
        const int g = lane >> 2, tq = lane & 3;
#pragma unroll
        for (int i = 0; i < 2; i++) {
            float mxa = -CUDART_INF_F, mxb = -CUDART_INF_F;
#pragma unroll
            for (int j = 0; j < 4; j++) {
                mxa = fmaxf(mxa, fmaxf(acc[i][j][0], acc[i][j][1]));
                mxb = fmaxf(mxb, fmaxf(acc[i][j][2], acc[i][j][3]));
            }
            mxa = fmaxf(mxa, __shfl_xor_sync(0xffffffffu, mxa, 1));
            mxa = fmaxf(mxa, __shfl_xor_sync(0xffffffffu, mxa, 2));
            mxb = fmaxf(mxb, __shfl_xor_sync(0xffffffffu, mxb, 1));
            mxb = fmaxf(mxb, __shfl_xor_sync(0xffffffffu, mxb, 2));
            float sa = 0.0f, sbx = 0.0f;
#pragma unroll
            for (int j = 0; j < 4; j++) {
                sa  += __expf(acc[i][j][0] - mxa) + __expf(acc[i][j][1] - mxa);
                sbx += __expf(acc[i][j][2] - mxb) + __expf(acc[i][j][3] - mxb);
            }
            sa  += __shfl_xor_sync(0xffffffffu, sa, 1);
            sa  += __shfl_xor_sync(0xffffffffu, sa, 2);
            sbx += __shfl_xor_sync(0xffffffffu, sbx, 1);
            sbx += __shfl_xor_sync(0xffffffffu, sbx, 2);
            if (tq == 0) {
                const int r0 = wr + 16 * i + g;
                pm[cg * 128 + r0]     = mxa;  pl[cg * 128 + r0]     = sa;
                pm[cg * 128 + r0 + 8] = mxb;  pl[cg * 128 + r0 + 8] = sbx;
            }
        }
        __syncthreads();

        if (tid < 128) {
            const float m0 = pm[tid], m1 = pm[128 + tid];
            const float m12 = fmaxf(m0, m1);
            const float l12 = pl[tid] * __expf(m0 - m12) +
                              pl[128 + tid] * __expf(m1 - m12);
            const float M = row_m[tid];
            const float nm = fmaxf(M, m12);
            row_l[tid] = row_l[tid] * __expf(M - nm) + l12 * __expf(m12 - nm);
            row_m[tid] = nm;
        }
        __syncthreads();
    }

    if (tid < 128) {
        g_mp[blockIdx.x * L + rowblk + tid] = row_m[tid];
        g_lp[blockIdx.x * L + rowblk + tid] = row_l[tid];
    }
}

// ---------------------------------------------------------------------------
// Kernel B: recompute QK^T per tile, softmax-normalize, write S once,
// PV MMA accumulating O in registers; combine folded into prologue.
// ---------------------------------------------------------------------------
__global__ __launch_bounds__(NT, 2) void fusedB_kernel(float* __restrict__ S,
                                                       float* __restrict__ O) {
    extern __shared__ char smem[];
    const uint32_t sb = smem_to_u32(smem);
    const int tid  = threadIdx.x;
    const int lane = tid & 31;
    const int w    = tid >> 5;
    const int wr   = (w & 3) * 32;      // QK phase warp tile
    const int wc   = (w >> 2) * 32;
    const int wr2  = 16 * w;            // PV phase warp rows
    const int rowblk  = blockIdx.y * BM;
    const int colbase = blockIdx.x * CHUNK;

    float* m_s  = (float*)(smem + B_STATS);
    float* li_s = m_s + 128;

    // prologue: Q limbs + K(0)  [group0],  V(0)  [group1]
#pragma unroll
    for (int i = 0; i < 8; i++) {
        const int idx = tid + i * NT;
        const int limb = idx >> 10, rem = idx & 1023;
        const int r = rem >> 3, c = rem & 7;
        const __nv_bfloat16* src =
            (limb ? gQl : gQh) + (size_t)(rowblk + r) * D + c * 8;
        CP_ASYNC16(sb + (limb ? BQL : BQH) + swo(r, c), src);
    }
#pragma unroll
    for (int i = 0; i < 4; i++) {
        const int idx = tid + i * NT;
        const int limb = idx >> 9, rem = idx & 511;
        const int r = rem >> 3, c = rem & 7;
        const __nv_bfloat16* src =
            (limb ? gKl : gKh) + (size_t)(colbase + r) * D + c * 8;
        CP_ASYNC16(sb + BKH + limb * 8192 + swo(r, c), src);
    }
    CP_COMMIT();
#pragma unroll
    for (int i = 0; i < 4; i++) {
        const int idx = tid + i * NT;
        const int limb = idx >> 9, rem = idx & 511;
        const int r = rem >> 3, c = rem & 7;
        const __nv_bfloat16* src =
            (limb ? gVl : gVh) + (size_t)(colbase + r) * D + c * 8;
        CP_ASYNC16(sb + BVH + limb * 8192 + swo(r, c), src);
    }
    CP_COMMIT();

    // fold stats combine into prologue
    if (tid < 128) {
        const int row = rowblk + tid;
        float m = -CUDART_INF_F;
#pragma unroll
        for (int c = 0; c < NCH; c++) m = fmaxf(m, g_mp[c * L + row]);
        float l = 0.0f;
#pragma unroll
        for (int c = 0; c < NCH; c++)
            l += g_lp[c * L + row] * __expf(g_mp[c * L + row] - m);
        m_s[tid]  = m;
        li_s[tid] = 1.0f / l;
    }

    float oacc[8][4];
#pragma unroll
    for (int j = 0; j < 8; j++)
#pragma unroll
        for (int e = 0; e < 4; e++) oacc[j][e] = 0.0f;

    const int a_row = (lane & 7) + (lane & 8);
    const int a_c   = (lane >> 4) & 1;
    const int b_n   = (lane & 7) + ((lane >> 4) & 1) * 8;
    const int b_c   = (lane >> 3) & 1;
    const int bt_k  = (lane & 7) + (lane & 8);
    const int bt_c  = (lane >> 4) & 1;
    const int g = lane >> 2, tq = lane & 3;

    for (int t = 0; t < NTIL; t++) {
        const int kb = colbase + t * BN;

        CP_WAIT(1);          // drain K(t) (and Q on t=0)
        __syncthreads();     // also guards P smem from prev PV

        // ---- QK^T MMA ----
        float acc[2][4][4];
#pragma unroll
        for (int i = 0; i < 2; i++)
#pragma unroll
            for (int j = 0; j < 4; j++)
#pragma unroll
                for (int e = 0; e < 4; e++) acc[i][j][e] = 0.0f;

#pragma unroll
        for (int ks = 0; ks < 4; ks++) {
            uint32_t aH[2][4], aL[2][4];
#pragma unroll
            for (int i = 0; i < 2; i++) {
                const uint32_t ao = swo(wr + 16 * i + a_row, ks * 2 + a_c);
                ldsm_x4(aH[i], sb + BQH + ao);
                ldsm_x4(aL[i], sb + BQL + ao);
            }
#pragma unroll
            for (int jj = 0; jj < 2; jj++) {
                const uint32_t bo = swo(wc + jj * 16 + b_n, ks * 2 + b_c);
                uint32_t bh[4], bl[4];
                ldsm_x4(bh, sb + BKH + bo);
                ldsm_x4(bl, sb + BKL + bo);
#pragma unroll
                for (int i = 0; i < 2; i++)
#pragma unroll
                    for (int p = 0; p < 2; p++) {
                        float* c = acc[i][2 * jj + p];
                        mma_bf16(c, aH[i], bh[2 * p], bh[2 * p + 1]);
                        mma_bf16(c, aH[i], bl[2 * p], bl[2 * p + 1]);
                        mma_bf16(c, aL[i], bh[2 * p], bh[2 * p + 1]);
                    }
            }
        }

        // ---- softmax epilogue: write normalized S + P limbs to smem ----
#pragma unroll
        for (int i = 0; i < 2; i++) {
            const int rl0 = wr + 16 * i + g;        // local rows rl0, rl0+8
            const float mi0 = m_s[rl0],     sc0 = li_s[rl0];
            const float mi1 = m_s[rl0 + 8], sc1 = li_s[rl0 + 8];
#pragma unroll
            for (int j = 0; j < 4; j++) {
                const int cl = wc + 2 * tq + 8 * j;  // local col
                const float p0 = __expf(acc[i][j][0] - mi0) * sc0;
                const float p1 = __expf(acc[i][j][1] - mi0) * sc0;
                const float p2 = __expf(acc[i][j][2] - mi1) * sc1;
                const float p3 = __expf(acc[i][j][3] - mi1) * sc1;
                *(float2*)&S[(size_t)(rowblk + rl0) * L + kb + cl] =
                    make_float2(p0, p1);
                *(float2*)&S[(size_t)(rowblk + rl0 + 8) * L + kb + cl] =
                    make_float2(p2, p3);
                __nv_bfloat162 h2, l2;
                const uint32_t o0 = swo(rl0, (cl >> 3)) + (cl & 7) * 2;
                split2(p0, p1, h2, l2);
                *(__nv_bfloat162*)(smem + BPH + o0) = h2;
                *(__nv_bfloat162*)(smem + BPL + o0) = l2;
                const uint32_t o1 = swo(rl0 + 8, (cl >> 3)) + (cl & 7) * 2;
                split2(p2, p3, h2, l2);
                *(__nv_bfloat162*)(smem + BPH + o1) = h2;
                *(__nv_bfloat162*)(smem + BPL + o1) = l2;
            }
        }
        __syncthreads();     // P ready; K(t) free

        if (t + 1 < NTIL) {  // issue K(t+1) — overlaps PV MMA below
            const int kb1 = colbase + (t + 1) * BN;
#pragma unroll
            for (int i = 0; i < 4; i++) {
                const int idx = tid + i * NT;
                const int limb = idx >> 9, rem = idx & 511;
                const int r = rem >> 3, c = rem & 7;
                const __nv_bfloat16* src =
                    (limb ? gKl : gKh) + (size_t)(kb1 + r) * D + c * 8;
                CP_ASYNC16(sb + BKH + limb * 8192 + swo(r, c), src);
            }
            CP_COMMIT();
            CP_WAIT(1);      // drain V(t); K(t+1) stays in flight
        } else {
            CP_WAIT(0);
        }
        __syncthreads();

        // ---- PV MMA (accumulate O) ----
#pragma unroll
        for (int ks = 0; ks < 4; ks++) {
            uint32_t aH[4], aL[4];
            const uint32_t ao = swo(wr2 + a_row, ks * 2 + a_c);
            ldsm_x4(aH, sb + BPH + ao);
            ldsm_x4(aL, sb + BPL + ao);
#pragma unroll
            for (int jj = 0; jj < 4; jj++) {
                const uint32_t bo = swo(ks * 16 + bt_k, 2 * jj + bt_c);
                uint32_t bh[4], bl[4];
                ldsm_x4_t(bh, sb + BVH + bo);
                ldsm_x4_t(bl, sb + BVL + bo);
#pragma unroll
                for (int p = 0; p < 2; p++) {
                    float* c = oacc[2 * jj + p];
                    mma_bf16(c, aH, bh[2 * p], bh[2 * p + 1]);
                    mma_bf16(c, aH, bl[2 * p], bl[2 * p + 1]);
                    mma_bf16(c, aL, bh[2 * p], bh[2 * p + 1]);
                }
            }
        }
        __syncthreads();     // V(t) free

        if (t + 1 < NTIL) {  // issue V(t+1) — overlaps next tile's QK
            const int kb1 = colbase + (t + 1) * BN;
#pragma unroll
            for (int i = 0; i < 4; i++) {
                const int idx = tid + i * NT;
                const int limb = idx >> 9, rem = idx & 511;
                const int r = rem >> 3, c = rem & 7;
                const __nv_bfloat16* src =
                    (limb ? gVl : gVh) + (size_t)(kb1 + r) * D + c * 8;
                CP_ASYNC16(sb + BVH + limb * 8192 + swo(r, c), src);
            }
            CP_COMMIT();
        }
    }

    // epilogue: atomic-accumulate partial O (O pre-zeroed)
    const int ra = rowblk + wr2 + g;
#pragma unroll
    for (int j = 0; j < 8; j++) {
        atomicAdd(&O[(size_t)ra * D + 8 * j + 2 * tq],     oacc[j][0]);
        atomicAdd(&O[(size_t)ra * D + 8 * j + 2 * tq + 1], oacc[j][1]);
        atomicAdd(&O[(size_t)(ra + 8) * D + 8 * j + 2 * tq],     oacc[j][2]);
        atomicAdd(&O[(size_t)(ra + 8) * D + 8 * j + 2 * tq + 1], oacc[j][3]);
    }
}

extern "C" void kernel_launch(void* const* d_in, const int* in_sizes, int n_in,
                              void* d_out, int out_size) {
    const float* q = (const float*)d_in[0];
    const float* k = (const float*)d_in[1];
    const float* v = (const float*)d_in[2];

    float* out   = (float*)d_out;          // [L, D]
    float* score = out + (size_t)L * D;    // [L, L]

    cudaFuncSetAttribute(statsA_kernel,
                         cudaFuncAttributeMaxDynamicSharedMemorySize, A_SMEM);
    cudaFuncSetAttribute(fusedB_kernel,
                         cudaFuncAttributeMaxDynamicSharedMemorySize, B_SMEM);

    dim3 pgrid(L * D / (2 * 256), 3);
    prep_kernel<<<pgrid, 256>>>(q, k, v);
    zero_o_kernel<<<L * D / 4 / 256, 256>>>(out);

    dim3 grid(NCH, L / BM);
    statsA_kernel<<<grid, NT, A_SMEM>>>();
    fusedB_kernel<<<grid, NT, B_SMEM>>>(score, out);
}

// round 9
// speedup vs baseline: 1.0495x; 1.0495x over previous
#include <cuda_runtime.h>
#include <cuda_bf16.h>
#include <math_constants.h>
#include <cstdint>

#define L     8192
#define D     64
#define BM    128            // query rows per CTA
#define NCH   16
#define CHUNK 512            // L / NCH
#define BN1   64             // pass1 key-tile width
#define T1    8              // CHUNK / BN1
#define BN2   64             // pass2 key-tile width
#define T2    8              // CHUNK / BN2
#define NT    256

// ---------------- scratch (__device__ globals; no allocation allowed) -------
__device__ float g_mp[NCH * L];
__device__ float g_lp[NCH * L];
__device__ float g_m[L];
__device__ float g_li[L];
// 2-limb bf16 versions of Q, K, V (prep kernel fills once)
__device__ __nv_bfloat16 gQh[L * D], gQl[L * D];
__device__ __nv_bfloat16 gKh[L * D], gKl[L * D];
__device__ __nv_bfloat16 gVh[L * D], gVl[L * D];

// ---------------- helpers ---------------------------------------------------
__device__ __forceinline__ uint32_t smem_to_u32(const void* p) {
    uint32_t a;
    asm("{ .reg .u64 t; cvta.to.shared.u64 t, %1; cvt.u32.u64 %0, t; }"
        : "=r"(a) : "l"(p));
    return a;
}
#define CP_ASYNC16(dst, src) \
    asm volatile("cp.async.cg.shared.global [%0], [%1], 16;" \
                 :: "r"(dst), "l"(src) : "memory")
#define CP_COMMIT() asm volatile("cp.async.commit_group;" ::: "memory")
#define CP_WAIT(n)  asm volatile("cp.async.wait_group %0;" :: "n"(n) : "memory")
#define PREFETCH_L2(p) \
    asm volatile("prefetch.global.L2 [%0];" :: "l"(p))

__device__ __forceinline__ void ldsm_x4(uint32_t* r, uint32_t a) {
    asm volatile("ldmatrix.sync.aligned.m8n8.x4.shared.b16 {%0,%1,%2,%3}, [%4];"
                 : "=r"(r[0]), "=r"(r[1]), "=r"(r[2]), "=r"(r[3]) : "r"(a));
}
__device__ __forceinline__ void ldsm_x4_t(uint32_t* r, uint32_t a) {
    asm volatile("ldmatrix.sync.aligned.m8n8.x4.trans.shared.b16 {%0,%1,%2,%3}, [%4];"
                 : "=r"(r[0]), "=r"(r[1]), "=r"(r[2]), "=r"(r[3]) : "r"(a));
}
__device__ __forceinline__ void mma_bf16(float* c, const uint32_t* a,
                                         uint32_t b0, uint32_t b1) {
    asm volatile("mma.sync.aligned.m16n8k16.row.col.f32.bf16.bf16.f32 "
                 "{%0,%1,%2,%3}, {%4,%5,%6,%7}, {%8,%9}, {%0,%1,%2,%3};"
                 : "+f"(c[0]), "+f"(c[1]), "+f"(c[2]), "+f"(c[3])
                 : "r"(a[0]), "r"(a[1]), "r"(a[2]), "r"(a[3]), "r"(b0), "r"(b1));
}
__device__ __forceinline__ void split2(float x, float y,
                                       __nv_bfloat162& h2, __nv_bfloat162& l2) {
    __nv_bfloat16 hx = __float2bfloat16(x);
    __nv_bfloat16 hy = __float2bfloat16(y);
    h2.x = hx; h2.y = hy;
    l2.x = __float2bfloat16(x - __bfloat162float(hx));
    l2.y = __float2bfloat16(y - __bfloat162float(hy));
}
// SW128 swizzle: 128B rows, 16B chunks; chunk c of row r lives at c^(r&7)
__device__ __forceinline__ uint32_t swo(int r, int c16) {
    return (uint32_t)(r * 128 + ((c16 ^ (r & 7)) << 4));
}

// pass1 smem byte offsets (swizzled 128B rows)
#define SQH 0
#define SQL 16384
#define SK0 32768              // buf b at SK0 + b*16384 (hi +0, lo +8192)
#define P1_STATS 65536
#define P1_SMEM  (65536 + 3072)
// pass2 smem byte offsets
#define SPH 0
#define SPL 16384
#define SV0 32768              // buf b at SV0 + b*16384 (hi +0, lo +8192)
#define P2_STATS 65536
#define P2_SMEM  (65536 + 1024)

// ---------------------------------------------------------------------------
// Prep: split Q, K, V into bf16 hi/lo limb arrays
// ---------------------------------------------------------------------------
__global__ void prep_kernel(const float* __restrict__ Q,
                            const float* __restrict__ Km,
                            const float* __restrict__ V) {
    const int idx = blockIdx.x * 256 + threadIdx.x;    // float2 index
    const float* src; __nv_bfloat16 *dh, *dl;
    if (blockIdx.y == 0)      { src = Q;  dh = gQh; dl = gQl; }
    else if (blockIdx.y == 1) { src = Km; dh = gKh; dl = gKl; }
    else                      { src = V;  dh = gVh; dl = gVl; }
    const float2 v = *(const float2*)&src[idx * 2];
    __nv_bfloat162 h2, l2; split2(v.x, v.y, h2, l2);
    *(__nv_bfloat162*)&dh[idx * 2] = h2;
    *(__nv_bfloat162*)&dl[idx * 2] = l2;
}

__global__ void zero_o_kernel(float* __restrict__ O) {
    const int idx = blockIdx.x * 256 + threadIdx.x;
    *(float4*)&O[idx * 4] = make_float4(0.f, 0.f, 0.f, 0.f);
}

// ---------------------------------------------------------------------------
// Pass 1: S = Q K^T raw logits (mma.sync, 2-limb) + per-chunk (m,l)
// warps: 4 row x 2 col groups; warp tile 32x32; K double-buffered cp.async
// ---------------------------------------------------------------------------
__global__ __launch_bounds__(NT, 3) void pass1_kernel(float* __restrict__ S) {
    extern __shared__ char smem[];
    const uint32_t sb = smem_to_u32(smem);
    const int tid  = threadIdx.x;
    const int lane = tid & 31;
    const int w    = tid >> 5;
    const int wr   = (w & 3) * 32;
    const int wc   = (w >> 2) * 32;
    const int cg   = w >> 2;
    const int rowblk  = blockIdx.y * BM;
    const int colbase = blockIdx.x * CHUNK;

    float* row_m = (float*)(smem + P1_STATS);       // [128]
    float* row_l = row_m + 128;                     // [128]
    float* pm    = row_l + 128;                     // [2][128]
    float* pl    = pm + 256;                        // [2][128]

    // prologue: Q limbs + K tile 0 via cp.async (one group)
#pragma unroll
    for (int i = 0; i < 8; i++) {
        const int idx = tid + i * NT;                // 2048 chunks
        const int limb = idx >> 10, rem = idx & 1023;
        const int r = rem >> 3, c = rem & 7;
        const __nv_bfloat16* src =
            (limb ? gQl : gQh) + (size_t)(rowblk + r) * D + c * 8;
        CP_ASYNC16(sb + (limb ? SQL : SQH) + swo(r, c), src);
    }
#pragma unroll
    for (int i = 0; i < 4; i++) {
        const int idx = tid + i * NT;                // 1024 chunks
        const int limb = idx >> 9, rem = idx & 511;
        const int r = rem >> 3, c = rem & 7;
        const __nv_bfloat16* src =
            (limb ? gKl : gKh) + (size_t)(colbase + r) * D + c * 8;
        CP_ASYNC16(sb + SK0 + limb * 8192 + swo(r, c), src);
    }
    CP_COMMIT();
    if (tid < 128) { row_m[tid] = -CUDART_INF_F; row_l[tid] = 0.0f; }

    const int a_row = (lane & 7) + (lane & 8);
    const int a_c   = (lane >> 4) & 1;
    const int b_n   = (lane & 7) + ((lane >> 4) & 1) * 8;
    const int b_c   = (lane >> 3) & 1;

    for (int t = 0; t < T1; t++) {
        if (t + 1 < T1) {       // prefetch next K tile
            const int kb = colbase + (t + 1) * BN1;
            const uint32_t kd = sb + SK0 + ((t + 1) & 1) * 16384;
#pragma unroll
            for (int i = 0; i < 4; i++) {
                const int idx = tid + i * NT;
                const int limb = idx >> 9, rem = idx & 511;
                const int r = rem >> 3, c = rem & 7;
                const __nv_bfloat16* src =
                    (limb ? gKl : gKh) + (size_t)(kb + r) * D + c * 8;
                CP_ASYNC16(kd + limb * 8192 + swo(r, c), src);
            }
            CP_COMMIT();
            CP_WAIT(1);
        } else {
            CP_WAIT(0);
        }
        __syncthreads();

        const int kb = colbase + t * BN1;
        const uint32_t skh = sb + SK0 + (t & 1) * 16384;
        const uint32_t skl = skh + 8192;

        float acc[2][4][4];
#pragma unroll
        for (int i = 0; i < 2; i++)
#pragma unroll
            for (int j = 0; j < 4; j++)
#pragma unroll
                for (int e = 0; e < 4; e++) acc[i][j][e] = 0.0f;

#pragma unroll
        for (int ks = 0; ks < 4; ks++) {
            uint32_t aH[2][4], aL[2][4];
#pragma unroll
            for (int i = 0; i < 2; i++) {
                const uint32_t ao = swo(wr + 16 * i + a_row, ks * 2 + a_c);
                ldsm_x4(aH[i], sb + SQH + ao);
                ldsm_x4(aL[i], sb + SQL + ao);
            }
#pragma unroll
            for (int jj = 0; jj < 2; jj++) {
                const uint32_t bo = swo(wc + jj * 16 + b_n, ks * 2 + b_c);
                uint32_t bh[4], bl[4];
                ldsm_x4(bh, skh + bo);
                ldsm_x4(bl, skl + bo);
#pragma unroll
                for (int i = 0; i < 2; i++)
#pragma unroll
                    for (int p = 0; p < 2; p++) {
                        float* c = acc[i][2 * jj + p];
                        mma_bf16(c, aH[i], bh[2 * p], bh[2 * p + 1]);
                        mma_bf16(c, aH[i], bl[2 * p], bl[2 * p + 1]);
                        mma_bf16(c, aL[i], bh[2 * p], bh[2 * p + 1]);
                    }
            }
        }

        // epilogue: raw S (streaming stores) + warp-level row stats
        const int g = lane >> 2, tq = lane & 3;
#pragma unroll
        for (int i = 0; i < 2; i++) {
            const int ra = rowblk + wr + 16 * i + g;
            const int cb = kb + wc + 2 * tq;
#pragma unroll
            for (int j = 0; j < 4; j++) {
                __stcs((float2*)&S[(size_t)ra * L + cb + 8 * j],
                       make_float2(acc[i][j][0], acc[i][j][1]));
                __stcs((float2*)&S[(size_t)(ra + 8) * L + cb + 8 * j],
                       make_float2(acc[i][j][2], acc[i][j][3]));
            }
            float mxa = -CUDART_INF_F, mxb = -CUDART_INF_F;
#pragma unroll
            for (int j = 0; j < 4; j++) {
                mxa = fmaxf(mxa, fmaxf(acc[i][j][0], acc[i][j][1]));
                mxb = fmaxf(mxb, fmaxf(acc[i][j][2], acc[i][j][3]));
            }
            mxa = fmaxf(mxa, __shfl_xor_sync(0xffffffffu, mxa, 1));
            mxa = fmaxf(mxa, __shfl_xor_sync(0xffffffffu, mxa, 2));
            mxb = fmaxf(mxb, __shfl_xor_sync(0xffffffffu, mxb, 1));
            mxb = fmaxf(mxb, __shfl_xor_sync(0xffffffffu, mxb, 2));
            float sa = 0.0f, sbx = 0.0f;
#pragma unroll
            for (int j = 0; j < 4; j++) {
                sa  += __expf(acc[i][j][0] - mxa) + __expf(acc[i][j][1] - mxa);
                sbx += __expf(acc[i][j][2] - mxb) + __expf(acc[i][j][3] - mxb);
            }
            sa  += __shfl_xor_sync(0xffffffffu, sa, 1);
            sa  += __shfl_xor_sync(0xffffffffu, sa, 2);
            sbx += __shfl_xor_sync(0xffffffffu, sbx, 1);
            sbx += __shfl_xor_sync(0xffffffffu, sbx, 2);
            if (tq == 0) {
                const int r0 = wr + 16 * i + g;
                pm[cg * 128 + r0]     = mxa;  pl[cg * 128 + r0]     = sa;
                pm[cg * 128 + r0 + 8] = mxb;  pl[cg * 128 + r0 + 8] = sbx;
            }
        }
        __syncthreads();

        if (tid < 128) {
            const float m0 = pm[tid], m1 = pm[128 + tid];
            const float m12 = fmaxf(m0, m1);
            const float l12 = pl[tid] * __expf(m0 - m12) +
                              pl[128 + tid] * __expf(m1 - m12);
            const float M = row_m[tid];
            const float nm = fmaxf(M, m12);
            row_l[tid] = row_l[tid] * __expf(M - nm) + l12 * __expf(m12 - nm);
            row_m[tid] = nm;
        }
        __syncthreads();
    }

    if (tid < 128) {
        g_mp[blockIdx.x * L + rowblk + tid] = row_m[tid];
        g_lp[blockIdx.x * L + rowblk + tid] = row_l[tid];
    }
}

// ---------------------------------------------------------------------------
// Combine per-chunk stats into final per-row (m, 1/l)
// ---------------------------------------------------------------------------
__global__ void combine_kernel() {
    const int row = blockIdx.x * 256 + threadIdx.x;
    float m = -CUDART_INF_F;
#pragma unroll
    for (int c = 0; c < NCH; c++) m = fmaxf(m, g_mp[c * L + row]);
    float l = 0.0f;
#pragma unroll
    for (int c = 0; c < NCH; c++)
        l += g_lp[c * L + row] * __expf(g_mp[c * L + row] - m);
    g_m[row]  = m;
    g_li[row] = 1.0f / l;
}

// ---------------------------------------------------------------------------
// Pass 2: normalize S in place; O += P V via mma.sync + atomics.
// V limbs double-buffered cp.async; next S tile prefetched to L2 (no regs).
// ---------------------------------------------------------------------------
__global__ __launch_bounds__(NT, 3) void pass2_kernel(float* __restrict__ S,
                                                      float* __restrict__ O) {
    extern __shared__ char smem[];
    const uint32_t sb = smem_to_u32(smem);
    const int tid  = threadIdx.x;
    const int lane = tid & 31;
    const int w    = tid >> 5;
    const int wr   = 16 * w;
    const int rowblk  = blockIdx.y * BM;
    const int colbase = blockIdx.x * CHUNK;

    float* m_s  = (float*)(smem + P2_STATS);
    float* li_s = m_s + 128;
    if (tid < 128) {
        m_s[tid]  = g_m[rowblk + tid];
        li_s[tid] = g_li[rowblk + tid];
    }

    // prologue: V tile 0
#pragma unroll
    for (int i = 0; i < 4; i++) {
        const int idx = tid + i * NT;                // 1024 chunks
        const int limb = idx >> 9, rem = idx & 511;
        const int r = rem >> 3, c = rem & 7;
        const __nv_bfloat16* src =
            (limb ? gVl : gVh) + (size_t)(colbase + r) * D + c * 8;
        CP_ASYNC16(sb + SV0 + limb * 8192 + swo(r, c), src);
    }
    CP_COMMIT();

    // L2 prefetch of S tile 0
    {
        const int r = tid >> 1, half = tid & 1;
        PREFETCH_L2(&S[(size_t)(rowblk + r) * L + colbase + half * 32]);
    }

    float acc[8][4];
#pragma unroll
    for (int j = 0; j < 8; j++)
#pragma unroll
        for (int e = 0; e < 4; e++) acc[j][e] = 0.0f;

    const int a_row = (lane & 7) + (lane & 8);
    const int a_c   = (lane >> 4) & 1;
    const int bt_k  = (lane & 7) + (lane & 8);
    const int bt_c  = (lane >> 4) & 1;

    __syncthreads();   // stats visible

    for (int t = 0; t < T2; t++) {
        const int kb = colbase + t * BN2;

        if (t + 1 < T2) {   // prefetch next V tile
            const int kb1 = colbase + (t + 1) * BN2;
            const uint32_t vd = sb + SV0 + ((t + 1) & 1) * 16384;
#pragma unroll
            for (int i = 0; i < 4; i++) {
                const int idx = tid + i * NT;
                const int limb = idx >> 9, rem = idx & 511;
                const int r = rem >> 3, c = rem & 7;
                const __nv_bfloat16* src =
                    (limb ? gVl : gVh) + (size_t)(kb1 + r) * D + c * 8;
                CP_ASYNC16(vd + limb * 8192 + swo(r, c), src);
            }
            CP_COMMIT();
            // L2 prefetch of next S tile (no register cost)
            const int r = tid >> 1, half = tid & 1;
            PREFETCH_L2(&S[(size_t)(rowblk + r) * L + kb1 + half * 32]);
        }

        // convert: read raw S, normalize, write back, split limbs to smem
#pragma unroll
        for (int i = 0; i < 8; i++) {
            const int idx = i * NT + tid;
            const int r = idx >> 4, c4 = idx & 15;
            float* sp = &S[(size_t)(rowblk + r) * L + kb + c4 * 4];
            const float4 s4 = __ldcs((const float4*)sp);
            const float mi = m_s[r], sc = li_s[r];
            float4 p4;
            p4.x = __expf(s4.x - mi) * sc;
            p4.y = __expf(s4.y - mi) * sc;
            p4.z = __expf(s4.z - mi) * sc;
            p4.w = __expf(s4.w - mi) * sc;
            __stcs((float4*)sp, p4);
            const uint32_t off = swo(r, c4 >> 1) + (c4 & 1) * 8;
            __nv_bfloat162 h2, l2;
            split2(p4.x, p4.y, h2, l2);
            *(__nv_bfloat162*)(smem + SPH + off) = h2;
            *(__nv_bfloat162*)(smem + SPL + off) = l2;
            split2(p4.z, p4.w, h2, l2);
            *(__nv_bfloat162*)(smem + SPH + off + 4) = h2;
            *(__nv_bfloat162*)(smem + SPL + off + 4) = l2;
        }
        if (t + 1 < T2) { CP_WAIT(1); } else { CP_WAIT(0); }
        __syncthreads();

        const uint32_t svh = sb + SV0 + (t & 1) * 16384;
        const uint32_t svl = svh + 8192;
#pragma unroll
        for (int ks = 0; ks < 4; ks++) {
            uint32_t aH[4], aL[4];
            const uint32_t ao = swo(wr + a_row, ks * 2 + a_c);
            ldsm_x4(aH, sb + SPH + ao);
            ldsm_x4(aL, sb + SPL + ao);
#pragma unroll
            for (int jj = 0; jj < 4; jj++) {
                const uint32_t bo = swo(ks * 16 + bt_k, 2 * jj + bt_c);
                uint32_t bh[4], bl[4];
                ldsm_x4_t(bh, svh + bo);
                ldsm_x4_t(bl, svl + bo);
#pragma unroll
                for (int p = 0; p < 2; p++) {
                    float* c = acc[2 * jj + p];
                    mma_bf16(c, aH, bh[2 * p], bh[2 * p + 1]);
                    mma_bf16(c, aH, bl[2 * p], bl[2 * p + 1]);
                    mma_bf16(c, aL, bh[2 * p], bh[2 * p + 1]);
                }
            }
        }
        __syncthreads();
    }

    // epilogue: atomic-accumulate partial O (O pre-zeroed)
    const int g = lane >> 2, tq = lane & 3;
    const int ra = rowblk + wr + g;
#pragma unroll
    for (int j = 0; j < 8; j++) {
        atomicAdd(&O[(size_t)ra * D + 8 * j + 2 * tq],     acc[j][0]);
        atomicAdd(&O[(size_t)ra * D + 8 * j + 2 * tq + 1], acc[j][1]);
        atomicAdd(&O[(size_t)(ra + 8) * D + 8 * j + 2 * tq],     acc[j][2]);
        atomicAdd(&O[(size_t)(ra + 8) * D + 8 * j + 2 * tq + 1], acc[j][3]);
    }
}

extern "C" void kernel_launch(void* const* d_in, const int* in_sizes, int n_in,
                              void* d_out, int out_size) {
    const float* q = (const float*)d_in[0];
    const float* k = (const float*)d_in[1];
    const float* v = (const float*)d_in[2];

    float* out   = (float*)d_out;          // [L, D]
    float* score = out + (size_t)L * D;    // [L, L]

    cudaFuncSetAttribute(pass1_kernel,
                         cudaFuncAttributeMaxDynamicSharedMemorySize, P1_SMEM);
    cudaFuncSetAttribute(pass2_kernel,
                         cudaFuncAttributeMaxDynamicSharedMemorySize, P2_SMEM);

    dim3 pgrid(L * D / (2 * 256), 3);
    prep_kernel<<<pgrid, 256>>>(q, k, v);
    zero_o_kernel<<<L * D / 4 / 256, 256>>>(out);

    dim3 grid(NCH, L / BM);
    pass1_kernel<<<grid, NT, P1_SMEM>>>(score);
    combine_kernel<<<L / 256, 256>>>();
    pass2_kernel<<<grid, NT, P2_SMEM>>>(score, out);
}

// round 11
// speedup vs baseline: 1.2235x; 1.1659x over previous
#include <cuda_runtime.h>
#include <cuda_bf16.h>
#include <math_constants.h>
#include <cstdint>

#define L     8192
#define D     64
#define BM    128            // query rows per CTA
#define NCH   8
#define CHUNK 1024           // L / NCH
#define BN1   64             // pass1 key-tile width
#define T1    16             // CHUNK / BN1
#define BN2   64             // pass2 key-tile width
#define T2    16             // CHUNK / BN2
#define NT    256

// ---------------- scratch (__device__ globals; no allocation allowed) -------
__device__ float g_l[L];     // row sums of exp(s), atomically accumulated
// 2-limb bf16 versions of Q, K, V (prep kernel fills once)
__device__ __nv_bfloat16 gQh[L * D], gQl[L * D];
__device__ __nv_bfloat16 gKh[L * D], gKl[L * D];
__device__ __nv_bfloat16 gVh[L * D], gVl[L * D];

// ---------------- helpers ---------------------------------------------------
__device__ __forceinline__ uint32_t smem_to_u32(const void* p) {
    uint32_t a;
    asm("{ .reg .u64 t; cvta.to.shared.u64 t, %1; cvt.u32.u64 %0, t; }"
        : "=r"(a) : "l"(p));
    return a;
}
#define CP_ASYNC16(dst, src) \
    asm volatile("cp.async.cg.shared.global [%0], [%1], 16;" \
                 :: "r"(dst), "l"(src) : "memory")
#define CP_COMMIT() asm volatile("cp.async.commit_group;" ::: "memory")
#define CP_WAIT(n)  asm volatile("cp.async.wait_group %0;" :: "n"(n) : "memory")

__device__ __forceinline__ void ldsm_x4(uint32_t* r, uint32_t a) {
    asm volatile("ldmatrix.sync.aligned.m8n8.x4.shared.b16 {%0,%1,%2,%3}, [%4];"
                 : "=r"(r[0]), "=r"(r[1]), "=r"(r[2]), "=r"(r[3]) : "r"(a));
}
__device__ __forceinline__ void ldsm_x4_t(uint32_t* r, uint32_t a) {
    asm volatile("ldmatrix.sync.aligned.m8n8.x4.trans.shared.b16 {%0,%1,%2,%3}, [%4];"
                 : "=r"(r[0]), "=r"(r[1]), "=r"(r[2]), "=r"(r[3]) : "r"(a));
}
__device__ __forceinline__ void mma_bf16(float* c, const uint32_t* a,
                                         uint32_t b0, uint32_t b1) {
    asm volatile("mma.sync.aligned.m16n8k16.row.col.f32.bf16.bf16.f32 "
                 "{%0,%1,%2,%3}, {%4,%5,%6,%7}, {%8,%9}, {%0,%1,%2,%3};"
                 : "+f"(c[0]), "+f"(c[1]), "+f"(c[2]), "+f"(c[3])
                 : "r"(a[0]), "r"(a[1]), "r"(a[2]), "r"(a[3]), "r"(b0), "r"(b1));
}
__device__ __forceinline__ void split2(float x, float y,
                                       __nv_bfloat162& h2, __nv_bfloat162& l2) {
    __nv_bfloat16 hx = __float2bfloat16(x);
    __nv_bfloat16 hy = __float2bfloat16(y);
    h2.x = hx; h2.y = hy;
    l2.x = __float2bfloat16(x - __bfloat162float(hx));
    l2.y = __float2bfloat16(y - __bfloat162float(hy));
}
// SW128 swizzle: 128B rows, 16B chunks; chunk c of row r lives at c^(r&7)
__device__ __forceinline__ uint32_t swo(int r, int c16) {
    return (uint32_t)(r * 128 + ((c16 ^ (r & 7)) << 4));
}

// pass1 smem byte offsets (swizzled 128B rows)
#define SQH 0
#define SQL 16384
#define SK0 32768              // buf b at SK0 + b*16384 (hi +0, lo +8192)
#define P1_SMEM  65536
// pass2 smem byte offsets
#define SPH 0
#define SPL 16384
#define SV0 32768              // buf b at SV0 + b*16384 (hi +0, lo +8192)
#define P2_STATS 65536
#define P2_SMEM  (65536 + 512)

// ---------------------------------------------------------------------------
// Prep: split Q, K, V into bf16 hi/lo limb arrays
// ---------------------------------------------------------------------------
__global__ void prep_kernel(const float* __restrict__ Q,
                            const float* __restrict__ Km,
                            const float* __restrict__ V) {
    const int idx = blockIdx.x * 256 + threadIdx.x;    // float2 index
    const float* src; __nv_bfloat16 *dh, *dl;
    if (blockIdx.y == 0)      { src = Q;  dh = gQh; dl = gQl; }
    else if (blockIdx.y == 1) { src = Km; dh = gKh; dl = gKl; }
    else                      { src = V;  dh = gVh; dl = gVl; }
    const float2 v = *(const float2*)&src[idx * 2];
    __nv_bfloat162 h2, l2; split2(v.x, v.y, h2, l2);
    *(__nv_bfloat162*)&dh[idx * 2] = h2;
    *(__nv_bfloat162*)&dl[idx * 2] = l2;
}

// zero O (L*D floats) and g_l (L floats)
__global__ void zero_kernel(float* __restrict__ O) {
    const int idx = blockIdx.x * 256 + threadIdx.x;    // float4 index
    *(float4*)&O[idx * 4] = make_float4(0.f, 0.f, 0.f, 0.f);
    if (idx < L / 4)
        *(float4*)&g_l[idx * 4] = make_float4(0.f, 0.f, 0.f, 0.f);
}

// ---------------------------------------------------------------------------
// Pass 1: S = exp(Q K^T) (no max shift) + register-resident row sums
// warps: 4 row x 2 col groups; warp tile 32x32; K double-buffered cp.async
// ---------------------------------------------------------------------------
__global__ __launch_bounds__(NT, 3) void pass1_kernel(float* __restrict__ S) {
    extern __shared__ char smem[];
    const uint32_t sb = smem_to_u32(smem);
    const int tid  = threadIdx.x;
    const int lane = tid & 31;
    const int w    = tid >> 5;
    const int wr   = (w & 3) * 32;
    const int wc   = (w >> 2) * 32;
    const int rowblk  = blockIdx.y * BM;
    const int colbase = blockIdx.x * CHUNK;

    // prologue: Q limbs + K tile 0 via cp.async (one group)
#pragma unroll
    for (int i = 0; i < 8; i++) {
        const int idx = tid + i * NT;                // 2048 chunks
        const int limb = idx >> 10, rem = idx & 1023;
        const int r = rem >> 3, c = rem & 7;
        const __nv_bfloat16* src =
            (limb ? gQl : gQh) + (size_t)(rowblk + r) * D + c * 8;
        CP_ASYNC16(sb + (limb ? SQL : SQH) + swo(r, c), src);
    }
#pragma unroll
    for (int i = 0; i < 4; i++) {
        const int idx = tid + i * NT;                // 1024 chunks
        const int limb = idx >> 9, rem = idx & 511;
        const int r = rem >> 3, c = rem & 7;
        const __nv_bfloat16* src =
            (limb ? gKl : gKh) + (size_t)(colbase + r) * D + c * 8;
        CP_ASYNC16(sb + SK0 + limb * 8192 + swo(r, c), src);
    }
    CP_COMMIT();

    const int a_row = (lane & 7) + (lane & 8);
    const int a_c   = (lane >> 4) & 1;
    const int b_n   = (lane & 7) + ((lane >> 4) & 1) * 8;
    const int b_c   = (lane >> 3) & 1;
    const int g = lane >> 2, tq = lane & 3;

    float rsum[2][2] = {{0.f, 0.f}, {0.f, 0.f}};   // [i][rowhalf]

    for (int t = 0; t < T1; t++) {
        if (t + 1 < T1) {       // prefetch next K tile
            const int kb = colbase + (t + 1) * BN1;
            const uint32_t kd = sb + SK0 + ((t + 1) & 1) * 16384;
#pragma unroll
            for (int i = 0; i < 4; i++) {
                const int idx = tid + i * NT;
                const int limb = idx >> 9, rem = idx & 511;
                const int r = rem >> 3, c = rem & 7;
                const __nv_bfloat16* src =
                    (limb ? gKl : gKh) + (size_t)(kb + r) * D + c * 8;
                CP_ASYNC16(kd + limb * 8192 + swo(r, c), src);
            }
            CP_COMMIT();
            CP_WAIT(1);
        } else {
            CP_WAIT(0);
        }
        __syncthreads();

        const int kb = colbase + t * BN1;
        const uint32_t skh = sb + SK0 + (t & 1) * 16384;
        const uint32_t skl = skh + 8192;

        float acc[2][4][4];
#pragma unroll
        for (int i = 0; i < 2; i++)
#pragma unroll
            for (int j = 0; j < 4; j++)
#pragma unroll
                for (int e = 0; e < 4; e++) acc[i][j][e] = 0.0f;

#pragma unroll
        for (int ks = 0; ks < 4; ks++) {
            uint32_t aH[2][4], aL[2][4];
#pragma unroll
            for (int i = 0; i < 2; i++) {
                const uint32_t ao = swo(wr + 16 * i + a_row, ks * 2 + a_c);
                ldsm_x4(aH[i], sb + SQH + ao);
                ldsm_x4(aL[i], sb + SQL + ao);
            }
#pragma unroll
            for (int jj = 0; jj < 2; jj++) {
                const uint32_t bo = swo(wc + jj * 16 + b_n, ks * 2 + b_c);
                uint32_t bh[4], bl[4];
                ldsm_x4(bh, skh + bo);
                ldsm_x4(bl, skl + bo);
#pragma unroll
                for (int i = 0; i < 2; i++)
#pragma unroll
                    for (int p = 0; p < 2; p++) {
                        float* c = acc[i][2 * jj + p];
                        mma_bf16(c, aH[i], bh[2 * p], bh[2 * p + 1]);
                        mma_bf16(c, aH[i], bl[2 * p], bl[2 * p + 1]);
                        mma_bf16(c, aL[i], bh[2 * p], bh[2 * p + 1]);
                    }
            }
        }

        // epilogue (pure per-warp): e = exp(s); store e; accumulate row sums
#pragma unroll
        for (int i = 0; i < 2; i++) {
            const int ra = rowblk + wr + 16 * i + g;
            const int cb = kb + wc + 2 * tq;
#pragma unroll
            for (int j = 0; j < 4; j++) {
                const float e0 = __expf(acc[i][j][0]);
                const float e1 = __expf(acc[i][j][1]);
                const float e2 = __expf(acc[i][j][2]);
                const float e3 = __expf(acc[i][j][3]);
                *(float2*)&S[(size_t)ra * L + cb + 8 * j] = make_float2(e0, e1);
                *(float2*)&S[(size_t)(ra + 8) * L + cb + 8 * j] = make_float2(e2, e3);
                rsum[i][0] += e0 + e1;
                rsum[i][1] += e2 + e3;
            }
        }
        // REQUIRED: all warps must finish MMA(t) before anyone's next-iter
        // cp.async overwrites buffer t&1 (the race that broke R10).
        __syncthreads();
    }

    // final: reduce row sums within quad (covers warp's 32 cols) + atomic
#pragma unroll
    for (int i = 0; i < 2; i++)
#pragma unroll
        for (int h = 0; h < 2; h++) {
            float s = rsum[i][h];
            s += __shfl_xor_sync(0xffffffffu, s, 1);
            s += __shfl_xor_sync(0xffffffffu, s, 2);
            if (tq == 0)
                atomicAdd(&g_l[rowblk + wr + 16 * i + 8 * h + g], s);
        }
}

// ---------------------------------------------------------------------------
// Pass 2: normalize S in place (p = e / l); O += P V via mma.sync + atomics.
// Next-tile S loads interleaved into the convert loop; V double-buffered.
// ---------------------------------------------------------------------------
__global__ __launch_bounds__(NT, 2) void pass2_kernel(float* __restrict__ S,
                                                      float* __restrict__ O) {
    extern __shared__ char smem[];
    const uint32_t sb = smem_to_u32(smem);
    const int tid  = threadIdx.x;
    const int lane = tid & 31;
    const int w    = tid >> 5;
    const int wr   = 16 * w;
    const int rowblk  = blockIdx.y * BM;
    const int colbase = blockIdx.x * CHUNK;

    float* li_s = (float*)(smem + P2_STATS);
    if (tid < 128) li_s[tid] = 1.0f / g_l[rowblk + tid];

    // prologue: V tile 0 + S tile 0 into regs
#pragma unroll
    for (int i = 0; i < 4; i++) {
        const int idx = tid + i * NT;                // 1024 chunks
        const int limb = idx >> 9, rem = idx & 511;
        const int r = rem >> 3, c = rem & 7;
        const __nv_bfloat16* src =
            (limb ? gVl : gVh) + (size_t)(colbase + r) * D + c * 8;
        CP_ASYNC16(sb + SV0 + limb * 8192 + swo(r, c), src);
    }
    CP_COMMIT();

    float4 s4[8];
#pragma unroll
    for (int i = 0; i < 8; i++) {
        const int idx = i * NT + tid;
        const int r = idx >> 4, c4 = idx & 15;
        s4[i] = *(const float4*)&S[(size_t)(rowblk + r) * L + colbase + c4 * 4];
    }

    float acc[8][4];
#pragma unroll
    for (int j = 0; j < 8; j++)
#pragma unroll
        for (int e = 0; e < 4; e++) acc[j][e] = 0.0f;

    const int a_row = (lane & 7) + (lane & 8);
    const int a_c   = (lane >> 4) & 1;
    const int bt_k  = (lane & 7) + (lane & 8);
    const int bt_c  = (lane >> 4) & 1;

    __syncthreads();   // li_s visible

    for (int t = 0; t < T2; t++) {
        const int kb = colbase + t * BN2;

        if (t + 1 < T2) {   // prefetch next V tile
            const int kb1 = colbase + (t + 1) * BN2;
            const uint32_t vd = sb + SV0 + ((t + 1) & 1) * 16384;
#pragma unroll
            for (int i = 0; i < 4; i++) {
                const int idx = tid + i * NT;
                const int limb = idx >> 9, rem = idx & 511;
                const int r = rem >> 3, c = rem & 7;
                const __nv_bfloat16* src =
                    (limb ? gVl : gVh) + (size_t)(kb1 + r) * D + c * 8;
                CP_ASYNC16(vd + limb * 8192 + swo(r, c), src);
            }
            CP_COMMIT();
        }

        // convert (multiply only) + interleaved next-tile S reloads
#pragma unroll
        for (int i = 0; i < 8; i++) {
            const int idx = i * NT + tid;
            const int r = idx >> 4, c4 = idx & 15;
            const float sc = li_s[r];
            float4 p4;
            p4.x = s4[i].x * sc;
            p4.y = s4[i].y * sc;
            p4.z = s4[i].z * sc;
            p4.w = s4[i].w * sc;
            if (t + 1 < T2)   // reload immediately after consumption
                s4[i] = *(const float4*)&S[(size_t)(rowblk + r) * L +
                                           kb + BN2 + c4 * 4];
            *(float4*)&S[(size_t)(rowblk + r) * L + kb + c4 * 4] = p4;
            const uint32_t off = swo(r, c4 >> 1) + (c4 & 1) * 8;
            __nv_bfloat162 h2, l2;
            split2(p4.x, p4.y, h2, l2);
            *(__nv_bfloat162*)(smem + SPH + off) = h2;
            *(__nv_bfloat162*)(smem + SPL + off) = l2;
            split2(p4.z, p4.w, h2, l2);
            *(__nv_bfloat162*)(smem + SPH + off + 4) = h2;
            *(__nv_bfloat162*)(smem + SPL + off + 4) = l2;
        }
        if (t + 1 < T2) { CP_WAIT(1); } else { CP_WAIT(0); }
        __syncthreads();

        const uint32_t svh = sb + SV0 + (t & 1) * 16384;
        const uint32_t svl = svh + 8192;
#pragma unroll
        for (int ks = 0; ks < 4; ks++) {
            uint32_t aH[4], aL[4];
            const uint32_t ao = swo(wr + a_row, ks * 2 + a_c);
            ldsm_x4(aH, sb + SPH + ao);
            ldsm_x4(aL, sb + SPL + ao);
#pragma unroll
            for (int jj = 0; jj < 4; jj++) {
                const uint32_t bo = swo(ks * 16 + bt_k, 2 * jj + bt_c);
                uint32_t bh[4], bl[4];
                ldsm_x4_t(bh, svh + bo);
                ldsm_x4_t(bl, svl + bo);
#pragma unroll
                for (int p = 0; p < 2; p++) {
                    float* c = acc[2 * jj + p];
                    mma_bf16(c, aH, bh[2 * p], bh[2 * p + 1]);
                    mma_bf16(c, aH, bl[2 * p], bl[2 * p + 1]);
                    mma_bf16(c, aL, bh[2 * p], bh[2 * p + 1]);
                }
            }
        }
        __syncthreads();
    }

    // epilogue: atomic-accumulate partial O (O pre-zeroed)
    const int g = lane >> 2, tq = lane & 3;
    const int ra = rowblk + wr + g;
#pragma unroll
    for (int j = 0; j < 8; j++) {
        atomicAdd(&O[(size_t)ra * D + 8 * j + 2 * tq],     acc[j][0]);
        atomicAdd(&O[(size_t)ra * D + 8 * j + 2 * tq + 1], acc[j][1]);
        atomicAdd(&O[(size_t)(ra + 8) * D + 8 * j + 2 * tq],     acc[j][2]);
        atomicAdd(&O[(size_t)(ra + 8) * D + 8 * j + 2 * tq + 1], acc[j][3]);
    }
}

extern "C" void kernel_launch(void* const* d_in, const int* in_sizes, int n_in,
                              void* d_out, int out_size) {
    const float* q = (const float*)d_in[0];
    const float* k = (const float*)d_in[1];
    const float* v = (const float*)d_in[2];

    float* out   = (float*)d_out;          // [L, D]
    float* score = out + (size_t)L * D;    // [L, L]

    cudaFuncSetAttribute(pass1_kernel,
                         cudaFuncAttributeMaxDynamicSharedMemorySize, P1_SMEM);
    cudaFuncSetAttribute(pass2_kernel,
                         cudaFuncAttributeMaxDynamicSharedMemorySize, P2_SMEM);

    dim3 pgrid(L * D / (2 * 256), 3);
    prep_kernel<<<pgrid, 256>>>(q, k, v);
    zero_kernel<<<L * D / 4 / 256, 256>>>(out);

    dim3 grid(NCH, L / BM);
    pass1_kernel<<<grid, NT, P1_SMEM>>>(score);
    pass2_kernel<<<grid, NT, P2_SMEM>>>(score, out);
}